// round 15
// baseline (speedup 1.0000x reference)
#include <cuda_runtime.h>

#define NN 50000
#define EE 800000
#define RR 850000
#define EPS 1e-5f
#define GSMEM 51200   // (64*68 + 64*132) * 4 bytes

// ---------------- static scratch (no runtime allocation) --------------------
__device__ float g_xt[NN * 64];
__device__ float g_dsum[NN * 64];
__device__ float g_dsb[NN * 64];
__device__ float g_dsbT[NN * 64];
__device__ float g_msg[NN * 64];
__device__ float g_msgb[NN * 64];
__device__ float g_agg[NN * 64];
__device__ float g_tpre[NN * 64];
__device__ float g_u[NN * 64];
__device__ float g_sA[NN * 64];
__device__ float g_h2[(size_t)RR * 64];
__device__ int   g_indeg[NN];
__device__ int   g_outdeg[NN];
__device__ int   g_rowD[NN];     // CSR start offsets, edges grouped by dst
__device__ int   g_rowS[NN];     // CSR start offsets, edges grouped by src
__device__ int   g_curD[NN];
__device__ int   g_curS[NN];
__device__ int   g_csrD[EE];     // src node id per edge, grouped by dst
__device__ int2  g_permSD[EE];   // (src,dst) per src-sorted slot
__device__ float g_stat[8][64];  // 0/1 bn1 sum/sq, 2/3 bn2, 4/5 bnt, 6/7 bn3
__device__ float g_scale[8][64]; // 0/1 bn1 sc/sh, 2/3 bn2, 4/5 bnt, 6/7 bn3

// ---------------- helpers ----------------------------------------------------
__device__ __forceinline__ void fma2(unsigned long long& d,
                                     unsigned long long a, unsigned long long b) {
    asm("fma.rn.f32x2 %0, %1, %2, %0;" : "+l"(d) : "l"(a), "l"(b));
}
__device__ __forceinline__ unsigned long long dup2(float x) {
    unsigned long long r;
    asm("mov.b64 %0, {%1, %1};" : "=l"(r) : "f"(x));
    return r;
}
__device__ __forceinline__ unsigned long long pack2(float x, float y) {
    unsigned long long r;
    asm("mov.b64 %0, {%1, %2};" : "=l"(r) : "f"(x), "f"(y));
    return r;
}
__device__ __forceinline__ float2 unpack2(unsigned long long v) {
    float2 r;
    asm("mov.b64 {%0, %1}, %2;" : "=f"(r.x), "=f"(r.y) : "l"(v));
    return r;
}
__device__ __forceinline__ float4 add4(float4 a, float4 b) {
    return make_float4(a.x + b.x, a.y + b.y, a.z + b.z, a.w + b.w);
}
__device__ __forceinline__ float4 bnrelu4(float4 v, float4 sc, float4 sh) {
    float4 r;
    r.x = fmaxf(fmaf(v.x, sc.x, sh.x), 0.f);
    r.y = fmaxf(fmaf(v.y, sc.y, sh.y), 0.f);
    r.z = fmaxf(fmaf(v.z, sc.z, sh.z), 0.f);
    r.w = fmaxf(fmaf(v.w, sc.w, sh.w), 0.f);
    return r;
}

// ---------------- init: stats = 0, degrees = 0 -------------------------------
__global__ void k_init0() {
    int idx = blockIdx.x * 256 + threadIdx.x;        // 196*256 = 50176
    if (idx < 512) (&g_stat[0][0])[idx] = 0.f;
    if (idx < NN) { g_indeg[idx] = 0; g_outdeg[idx] = 0; }
}

// ---------------- degree counts ----------------------------------------------
__global__ void k_deg(const int* __restrict__ src, const int* __restrict__ dst) {
    int e = blockIdx.x * 256 + threadIdx.x;          // EE exact
    atomicAdd(&g_indeg[dst[e]], 1);
    atomicAdd(&g_outdeg[src[e]], 1);
}

// ---------------- single-kernel exclusive scan of both degree arrays ---------
// 1 block, 1024 threads: lower 512 scan indeg -> rowD/curD, upper 512 scan
// outdeg -> rowS/curS. Each thread owns a 98-element chunk (512*98 >= NN).
__global__ void __launch_bounds__(1024) k_scanAll() {
    __shared__ int sm[1024];
    int tid = threadIdx.x;
    int half = tid >> 9;                             // 0 = D, 1 = S
    int lt = tid & 511;
    const int* deg = half ? g_outdeg : g_indeg;
    int* row = half ? g_rowS : g_rowD;
    int* cur = half ? g_curS : g_curD;
    int begin = lt * 98;
    int end = begin + 98 < NN ? begin + 98 : NN;
    int sum = 0;
    for (int i = begin; i < end; i++) sum += deg[i];
    sm[tid] = sum;
    __syncthreads();
    for (int off = 1; off < 512; off <<= 1) {
        int t = (lt >= off) ? sm[tid - off] : 0;
        __syncthreads();
        sm[tid] += t;
        __syncthreads();
    }
    int run = sm[tid] - sum;                         // exclusive prefix
    for (int i = begin; i < end; i++) {
        row[i] = run; cur[i] = run;
        run += deg[i];
    }
}

// ---------------- CSR fill ---------------------------------------------------
__global__ void k_fill(const int* __restrict__ src, const int* __restrict__ dst) {
    int e = blockIdx.x * 256 + threadIdx.x;          // EE exact
    int s = src[e], d = dst[e];
    int pD = atomicAdd(&g_curD[d], 1);
    g_csrD[pD] = s;
    int pS = atomicAdd(&g_curS[s], 1);
    g_permSD[pS] = make_int2(s, d);
}

// ---------------- dsum[d] = x[d] + sum_{e:dst=d} x[src] (gather) -------------
__global__ void k_dsum_g(const float4* __restrict__ x4) {
    int tid = threadIdx.x;
    int d = blockIdx.x * 16 + (tid >> 4);            // 3125*16 = NN exact
    int c4 = tid & 15;
    float4 acc = x4[(size_t)d * 16 + c4];
    int start = g_rowD[d], len = g_indeg[d];
    int j = 0;
    for (; j + 1 < len; j += 2) {
        int a0 = g_csrD[start + j], a1 = g_csrD[start + j + 1];
        float4 v0 = x4[(size_t)a0 * 16 + c4];
        float4 v1 = x4[(size_t)a1 * 16 + c4];
        acc = add4(acc, add4(v0, v1));
    }
    if (j < len) acc = add4(acc, x4[(size_t)g_csrD[start + j] * 16 + c4]);
    ((float4*)g_dsum)[(size_t)d * 16 + c4] = acc;
}

// ---------------- N-row GEMM: out = in1@W1 [+ in2@W2] [+bias]; f32x2 FMA -----
__global__ void __launch_bounds__(256) k_gemm2(float* __restrict__ out,
                                               const float* __restrict__ in1,
                                               const float* __restrict__ W1,
                                               const float* __restrict__ in2,
                                               const float* __restrict__ W2,
                                               const float* __restrict__ bias,
                                               int relu, int si, int insc,
                                               float* __restrict__ out2,
                                               const float* __restrict__ in1b,
                                               const float* __restrict__ W1b,
                                               float* __restrict__ out3,
                                               const float* __restrict__ in1c,
                                               const float* __restrict__ W1c) {
    extern __shared__ float dynS[];
    float* Ws = dynS;              // [64][68]
    float* inT = dynS + 64 * 68;   // [64][132]
    __shared__ float statS[128];
    int tid = threadIdx.x;
    if (tid < 128) statS[tid] = 0.f;
    const float* inA = in1;
    const float* WA = W1;
    float* outp = out;
    int base;
    if (out3) {
        int third = gridDim.x / 3;
        int sgm = blockIdx.x / third;
        base = (blockIdx.x - sgm * third) * 128;
        if (sgm == 1) { inA = in1b; WA = W1b; outp = out2; }
        else if (sgm == 2) { inA = in1c; WA = W1c; outp = out3; }
    } else if (out2) {
        int half = gridDim.x >> 1;
        if (blockIdx.x >= half) {
            inA = in1b; WA = W1b; outp = out2;
            base = (blockIdx.x - half) * 128;
        } else base = blockIdx.x * 128;
    } else base = blockIdx.x * 128;
    int rg = tid >> 3, cg = tid & 7;
    int r0 = rg * 4, c0 = cg * 8;
    unsigned long long acc[4][4];
#pragma unroll
    for (int rr = 0; rr < 4; rr++)
#pragma unroll
        for (int jp = 0; jp < 4; jp++)
            acc[rr][jp] = bias ? pack2(bias[c0 + jp * 2], bias[c0 + jp * 2 + 1]) : 0ull;

#pragma unroll 1
    for (int p = 0; p < 2; p++) {
        const float* in = p ? in2 : inA;
        const float* W = p ? W2 : WA;
        if (!in) break;
        if (p) __syncthreads();
        for (int i = tid; i < 4096; i += 256) Ws[(i >> 6) * 68 + (i & 63)] = W[i];
        const float4* in4 = (const float4*)in;
        int xf = (p == 0 && insc >= 0);
        for (int i = tid; i < 2048; i += 256) {
            int r = i & 127, c4 = i >> 7;
            float4 v = make_float4(0.f, 0.f, 0.f, 0.f);
            if (base + r < NN) {
                v = in4[(size_t)(base + r) * 16 + c4];
                if (xf) v = bnrelu4(v, ((const float4*)g_scale[insc])[c4],
                                    ((const float4*)g_scale[insc + 1])[c4]);
            }
            int c = c4 * 4;
            inT[c * 132 + r] = v.x; inT[(c + 1) * 132 + r] = v.y;
            inT[(c + 2) * 132 + r] = v.z; inT[(c + 3) * 132 + r] = v.w;
        }
        __syncthreads();
#pragma unroll 4
        for (int k = 0; k < 64; k++) {
            float4 a4 = *(const float4*)&inT[k * 132 + r0];
            ulonglong2 w01 = *(const ulonglong2*)&Ws[k * 68 + c0];
            ulonglong2 w23 = *(const ulonglong2*)&Ws[k * 68 + c0 + 4];
            unsigned long long wp[4] = { w01.x, w01.y, w23.x, w23.y };
            unsigned long long ap[4] = { dup2(a4.x), dup2(a4.y), dup2(a4.z), dup2(a4.w) };
#pragma unroll
            for (int rr = 0; rr < 4; rr++)
#pragma unroll
                for (int jp = 0; jp < 4; jp++)
                    fma2(acc[rr][jp], ap[rr], wp[jp]);
        }
    }
    float lsum[8], lsq[8];
#pragma unroll
    for (int j = 0; j < 8; j++) { lsum[j] = 0.f; lsq[j] = 0.f; }
#pragma unroll
    for (int rr = 0; rr < 4; rr++) {
        int gr = base + r0 + rr;
        if (gr >= NN) break;
        float o[8];
#pragma unroll
        for (int jp = 0; jp < 4; jp++) {
            float2 u = unpack2(acc[rr][jp]);
            o[jp * 2] = u.x; o[jp * 2 + 1] = u.y;
        }
        if (relu) {
#pragma unroll
            for (int j = 0; j < 8; j++) o[j] = fmaxf(o[j], 0.f);
        }
        if (si >= 0) {
#pragma unroll
            for (int j = 0; j < 8; j++) { lsum[j] += o[j]; lsq[j] += o[j] * o[j]; }
        }
        float4* op = (float4*)(outp + (size_t)gr * 64 + c0);
        op[0] = make_float4(o[0], o[1], o[2], o[3]);
        op[1] = make_float4(o[4], o[5], o[6], o[7]);
    }
    if (si >= 0) {
        int lane = tid & 31;
#pragma unroll
        for (int j = 0; j < 8; j++) {
            float s_ = lsum[j], q_ = lsq[j];
            s_ += __shfl_xor_sync(0xFFFFFFFFu, s_, 8);
            s_ += __shfl_xor_sync(0xFFFFFFFFu, s_, 16);
            q_ += __shfl_xor_sync(0xFFFFFFFFu, q_, 8);
            q_ += __shfl_xor_sync(0xFFFFFFFFu, q_, 16);
            if (lane < 8) {
                atomicAdd(&statS[c0 + j], s_);
                atomicAdd(&statS[64 + c0 + j], q_);
            }
        }
        __syncthreads();
        if (tid < 64) {
            atomicAdd(&g_stat[si][tid], statS[tid]);
            atomicAdd(&g_stat[si + 1][tid], statS[64 + tid]);
        }
    }
}

// ---------------- BN1 stats: algebraic node-level pass -----------------------
__global__ void k_bn1_alg(const float* __restrict__ b_unite) {
    __shared__ float st[128];
    int tid = threadIdx.x;
    if (tid < 128) st[tid] = 0.f;
    __syncthreads();
    int idx = blockIdx.x * 256 + tid;                // NN*16 exact
    int i = idx >> 4, c4 = idx & 15;
    float4 X = ((const float4*)g_xt)[idx];
    float4 D = ((const float4*)g_dsb)[idx];
    float4 T = ((const float4*)g_dsbT)[idx];
    float4 b = ((const float4*)b_unite)[c4];
    float od = (float)g_outdeg[i], id = (float)g_indeg[i];
    float s1v[4], s2v[4];
    {
        float xs[4] = { X.x, X.y, X.z, X.w };
        float ds[4] = { D.x, D.y, D.z, D.w };
        float ts[4] = { T.x, T.y, T.z, T.w };
        float bs[4] = { b.x, b.y, b.z, b.w };
#pragma unroll
        for (int k = 0; k < 4; k++) {
            float v = xs[k] + ds[k] + bs[k];
            float e1 = od * xs[k] + id * ds[k];
            s1v[k] = v + e1;
            s2v[k] = v * v + od * xs[k] * xs[k] + id * ds[k] * ds[k]
                   + 2.f * (ts[k] - xs[k]) * ds[k] + 2.f * bs[k] * e1;
        }
    }
#pragma unroll
    for (int k = 0; k < 4; k++) {
        s1v[k] += __shfl_xor_sync(0xFFFFFFFFu, s1v[k], 16);
        s2v[k] += __shfl_xor_sync(0xFFFFFFFFu, s2v[k], 16);
    }
    if ((tid & 16) == 0) {
#pragma unroll
        for (int k = 0; k < 4; k++) {
            atomicAdd(&st[c4 * 4 + k], s1v[k]);
            atomicAdd(&st[64 + c4 * 4 + k], s2v[k]);
        }
    }
    __syncthreads();
    if (tid < 64) {
        atomicAdd(&g_stat[0][tid], st[tid]);
        atomicAdd(&g_stat[1][tid], st[64 + tid]);
    }
}

// ---------------- BN finalize into scale/shift -------------------------------
__global__ void k_bn_final(int si, float cnt, const float* __restrict__ g,
                           const float* __restrict__ be, const float* __restrict__ pb,
                           int oi, float cntE, const float* __restrict__ pe) {
    int c = threadIdx.x;
    float s = g_stat[si][c], q = g_stat[si + 1][c];
    if (pe) { s += cntE * pe[c]; q += cntE * pe[c] * pe[c]; }
    float m = s / cnt;
    float v = q / cnt - m * m;
    float sc = g[c] * rsqrtf(v + EPS);
    float sh = be[c] - m * sc;
    if (pb) sh += pb[c] * sc;
    g_scale[oi][c] = sc;
    g_scale[oi + 1][c] = sh;
}

// ---------------- s[d] = hn(d,d) + sum_{e:dst=d} hn(src,d) (gather) ----------
__global__ void k_s_g() {
    int tid = threadIdx.x;
    int d = blockIdx.x * 16 + (tid >> 4);
    int c4 = tid & 15;
    const float4* xt4 = (const float4*)g_xt;
    float4 dsb_d = ((const float4*)g_dsb)[(size_t)d * 16 + c4];
    float4 sc = ((const float4*)g_scale[0])[c4];
    float4 sh = ((const float4*)g_scale[1])[c4];
    float4 acc = bnrelu4(add4(xt4[(size_t)d * 16 + c4], dsb_d), sc, sh);
    int start = g_rowD[d], len = g_indeg[d];
    int j = 0;
    for (; j + 1 < len; j += 2) {
        int a0 = g_csrD[start + j], a1 = g_csrD[start + j + 1];
        float4 v0 = xt4[(size_t)a0 * 16 + c4];
        float4 v1 = xt4[(size_t)a1 * 16 + c4];
        acc = add4(acc, add4(bnrelu4(add4(v0, dsb_d), sc, sh),
                             bnrelu4(add4(v1, dsb_d), sc, sh)));
    }
    if (j < len)
        acc = add4(acc, bnrelu4(add4(xt4[(size_t)g_csrD[start + j] * 16 + c4], dsb_d), sc, sh));
    ((float4*)g_sA)[(size_t)d * 16 + c4] = acc;
}

// ---------------- msg[d] = sum_{e:dst=d} s[src] (gather) ---------------------
__global__ void k_msg_g() {
    int tid = threadIdx.x;
    int d = blockIdx.x * 16 + (tid >> 4);
    int c4 = tid & 15;
    const float4* s4 = (const float4*)g_sA;
    float4 acc = make_float4(0.f, 0.f, 0.f, 0.f);
    int start = g_rowD[d], len = g_indeg[d];
    int j = 0;
    for (; j + 1 < len; j += 2) {
        int a0 = g_csrD[start + j], a1 = g_csrD[start + j + 1];
        acc = add4(acc, add4(s4[(size_t)a0 * 16 + c4], s4[(size_t)a1 * 16 + c4]));
    }
    if (j < len) acc = add4(acc, s4[(size_t)g_csrD[start + j] * 16 + c4]);
    ((float4*)g_msg)[(size_t)d * 16 + c4] = acc;
}

// ---------------- hot: h2_pre (src-permuted edge rows) + fused BN2 stats -----
__global__ void __launch_bounds__(256) k_h2(const float* __restrict__ Wg) {
    extern __shared__ float dynS[];
    float* Ws = dynS;              // [64][68]
    float* hnT = dynS + 64 * 68;   // [64][132]
    __shared__ int domS[128];
    __shared__ float statS[128];
    int tid = threadIdx.x;
    for (int i = tid; i < 4096; i += 256) Ws[(i >> 6) * 68 + (i & 63)] = Wg[i];
    if (tid < 128) statS[tid] = 0.f;
    int rg = tid >> 3, cg = tid & 7;
    int r0 = rg * 4, c0 = cg * 8;
    const float4* xt4 = (const float4*)g_xt;
    const float4* db4 = (const float4*)g_dsb;
    const float4* sc4 = (const float4*)g_scale[0];
    const float4* sh4 = (const float4*)g_scale[1];
    const float4* mb4 = (const float4*)g_msgb;
    float lsum[8], lsq[8];
#pragma unroll
    for (int j = 0; j < 8; j++) { lsum[j] = 0.f; lsq[j] = 0.f; }
    __syncthreads();

    for (int t = 0; t < 4; t++) {
        long base = ((long)blockIdx.x * 4 + t) * 128;
        if (base >= RR) break;
        for (int i = tid; i < 2048; i += 256) {
            int r = i & 127, c4 = i >> 7;
            long gr = base + r;
            float4 v = make_float4(0.f, 0.f, 0.f, 0.f);
            int d = 0;
            if (gr < RR) {
                int a;
                if (gr < NN) { a = (int)gr; d = a; }
                else { int2 sd = g_permSD[gr - NN]; a = sd.x; d = sd.y; }
                v = bnrelu4(add4(xt4[(size_t)a * 16 + c4], db4[(size_t)d * 16 + c4]),
                            sc4[c4], sh4[c4]);
            }
            if (c4 == 0) domS[r] = d;
            int c = c4 * 4;
            hnT[c * 132 + r] = v.x; hnT[(c + 1) * 132 + r] = v.y;
            hnT[(c + 2) * 132 + r] = v.z; hnT[(c + 3) * 132 + r] = v.w;
        }
        __syncthreads();
        unsigned long long acc[4][4];
#pragma unroll
        for (int rr = 0; rr < 4; rr++)
#pragma unroll
            for (int jp = 0; jp < 4; jp++) acc[rr][jp] = 0ull;
#pragma unroll 4
        for (int k = 0; k < 64; k++) {
            float4 a4 = *(const float4*)&hnT[k * 132 + r0];
            ulonglong2 w01 = *(const ulonglong2*)&Ws[k * 68 + c0];
            ulonglong2 w23 = *(const ulonglong2*)&Ws[k * 68 + c0 + 4];
            unsigned long long wp[4] = { w01.x, w01.y, w23.x, w23.y };
            unsigned long long ap[4] = { dup2(a4.x), dup2(a4.y), dup2(a4.z), dup2(a4.w) };
#pragma unroll
            for (int rr = 0; rr < 4; rr++)
#pragma unroll
                for (int jp = 0; jp < 4; jp++)
                    fma2(acc[rr][jp], ap[rr], wp[jp]);
        }
#pragma unroll
        for (int rr = 0; rr < 4; rr++) {
            long gr = base + r0 + rr;
            if (gr >= RR) break;
            int dm = domS[r0 + rr];
            float4 m0 = mb4[(size_t)dm * 16 + cg * 2];
            float4 m1 = mb4[(size_t)dm * 16 + cg * 2 + 1];
            float mv[8] = { m0.x, m0.y, m0.z, m0.w, m1.x, m1.y, m1.z, m1.w };
            float o[8];
#pragma unroll
            for (int jp = 0; jp < 4; jp++) {
                float2 u = unpack2(acc[rr][jp]);
                o[jp * 2] = u.x + mv[jp * 2];
                o[jp * 2 + 1] = u.y + mv[jp * 2 + 1];
            }
#pragma unroll
            for (int j = 0; j < 8; j++) { lsum[j] += o[j]; lsq[j] += o[j] * o[j]; }
            float4* op = (float4*)(g_h2 + (size_t)gr * 64 + c0);
            op[0] = make_float4(o[0], o[1], o[2], o[3]);
            op[1] = make_float4(o[4], o[5], o[6], o[7]);
        }
        __syncthreads();
    }
    int lane = tid & 31;
#pragma unroll
    for (int j = 0; j < 8; j++) {
        float s_ = lsum[j], q_ = lsq[j];
        s_ += __shfl_xor_sync(0xFFFFFFFFu, s_, 8);
        s_ += __shfl_xor_sync(0xFFFFFFFFu, s_, 16);
        q_ += __shfl_xor_sync(0xFFFFFFFFu, q_, 8);
        q_ += __shfl_xor_sync(0xFFFFFFFFu, q_, 16);
        if (lane < 8) {
            atomicAdd(&statS[c0 + j], s_);
            atomicAdd(&statS[64 + c0 + j], q_);
        }
    }
    __syncthreads();
    if (tid < 64) {
        atomicAdd(&g_stat[2][tid], statS[tid]);
        atomicAdd(&g_stat[3][tid], statS[64 + tid]);
    }
}

// ---------------- agg[i] = u[i] + sum of contiguous src-sorted h2 rows -------
__global__ void k_agg_g() {
    int tid = threadIdx.x;
    int i = blockIdx.x * 16 + (tid >> 4);
    int c4 = tid & 15;
    const float4* h4 = (const float4*)g_h2;
    float4 sc = ((const float4*)g_scale[2])[c4];
    float4 sh = ((const float4*)g_scale[3])[c4];
    float4 uv = bnrelu4(h4[(size_t)i * 16 + c4], sc, sh);
    ((float4*)g_u)[(size_t)i * 16 + c4] = uv;
    float4 acc = uv;
    size_t rbase = (size_t)NN + g_rowS[i];
    int len = g_outdeg[i];
    int j = 0;
    for (; j + 1 < len; j += 2) {
        float4 v0 = h4[(rbase + j) * 16 + c4];
        float4 v1 = h4[(rbase + j + 1) * 16 + c4];
        acc = add4(acc, add4(bnrelu4(v0, sc, sh), bnrelu4(v1, sc, sh)));
    }
    if (j < len)
        acc = add4(acc, bnrelu4(h4[(rbase + j) * 16 + c4], sc, sh));
    ((float4*)g_agg)[(size_t)i * 16 + c4] = acc;
}

// ---------------- out = relu(in * scale + shift) -----------------------------
__global__ void k_bnrelu(float* __restrict__ out, const float* __restrict__ in, int sidx) {
    int idx = blockIdx.x * 256 + threadIdx.x;        // NN*16 exact
    int c4 = idx & 15;
    float4 v = ((const float4*)in)[idx];
    ((float4*)out)[idx] = bnrelu4(v, ((const float4*)g_scale[0] + (size_t)sidx * 16)[c4],
                                  ((const float4*)g_scale[0] + (size_t)(sidx + 1) * 16)[c4]);
}

extern "C" void kernel_launch(void* const* d_in, const int* in_sizes, int n_in,
                              void* d_out, int out_size) {
    const float* x   = (const float*)d_in[0];
    const int*   ei  = (const int*)d_in[1];
    const int*   src = ei;
    const int*   dst = ei + EE;
    const float* Wu  = (const float*)d_in[2];
    const float* bu  = (const float*)d_in[3];
    const float* g1  = (const float*)d_in[4];
    const float* be1 = (const float*)d_in[5];
    const float* Wg  = (const float*)d_in[6];
    const float* bg  = (const float*)d_in[7];
    const float* g2  = (const float*)d_in[8];
    const float* be2 = (const float*)d_in[9];
    const float* Wt  = (const float*)d_in[10];
    const float* bt  = (const float*)d_in[11];
    const float* Wl  = (const float*)d_in[12];
    const float* bl  = (const float*)d_in[13];
    const float* g3  = (const float*)d_in[14];
    const float* be3 = (const float*)d_in[15];

    static float *p_xt = nullptr, *p_dsum, *p_dsb, *p_dsbT, *p_msg, *p_msgb,
                 *p_agg, *p_tpre, *p_u;
    if (!p_xt) {
        cudaGetSymbolAddress((void**)&p_xt, g_xt);
        cudaGetSymbolAddress((void**)&p_dsum, g_dsum);
        cudaGetSymbolAddress((void**)&p_dsb, g_dsb);
        cudaGetSymbolAddress((void**)&p_dsbT, g_dsbT);
        cudaGetSymbolAddress((void**)&p_msg, g_msg);
        cudaGetSymbolAddress((void**)&p_msgb, g_msgb);
        cudaGetSymbolAddress((void**)&p_agg, g_agg);
        cudaGetSymbolAddress((void**)&p_tpre, g_tpre);
        cudaGetSymbolAddress((void**)&p_u, g_u);
        cudaFuncSetAttribute(k_gemm2, cudaFuncAttributeMaxDynamicSharedMemorySize, GSMEM);
        cudaFuncSetAttribute(k_h2, cudaFuncAttributeMaxDynamicSharedMemorySize, GSMEM);
    }

    // CSR build (single-kernel scan)
    k_init0<<<196, 256>>>();
    k_deg<<<3125, 256>>>(src, dst);
    k_scanAll<<<1, 1024>>>();
    k_fill<<<3125, 256>>>(src, dst);

    // unite: gather dsum, triple GEMM, algebraic BN1
    k_dsum_g<<<3125, 256>>>((const float4*)x);
    k_gemm2<<<1173, 256, GSMEM>>>(p_xt, x, Wu, nullptr, nullptr, nullptr, 0, -1, -1,
                                  p_dsb, p_dsum, Wu + 4096,
                                  p_dsbT, p_dsum, Wu);
    k_bn1_alg<<<3125, 256>>>(bu);
    k_bn_final<<<1, 64>>>(0, (float)RR, g1, be1, bu, 0, (float)EE, bu);

    // gconv: gather s, gather msg, msgb GEMM, h2 (src-permuted edge rows)
    k_s_g<<<3125, 256>>>();
    k_msg_g<<<3125, 256>>>();
    k_gemm2<<<391, 256, GSMEM>>>(p_msgb, p_msg, Wg + 4096, nullptr, nullptr, bg, 0, -1, -1,
                                 nullptr, nullptr, nullptr, nullptr, nullptr, nullptr);
    k_h2<<<1661, 256, GSMEM>>>(Wg);
    k_bn_final<<<1, 64>>>(2, (float)RR, g2, be2, nullptr, 2, 0.f, nullptr);

    // transfer: streaming agg (+u), fused dual GEMM + BNt stats
    k_agg_g<<<3125, 256>>>();
    k_gemm2<<<391, 256, GSMEM>>>(p_tpre, p_u, Wt, p_agg, Wt + 4096, bt, 0, 4, -1,
                                 nullptr, nullptr, nullptr, nullptr, nullptr, nullptr);
    k_bn_final<<<1, 64>>>(4, (float)NN, g2, be2, nullptr, 4, 0.f, nullptr);

    // final linear with fused input bnrelu(t) transform; relu + BN3 stats
    k_gemm2<<<391, 256, GSMEM>>>(p_u, p_tpre, Wl, nullptr, nullptr, bl, 1, 6, 4,
                                 nullptr, nullptr, nullptr, nullptr, nullptr, nullptr);
    k_bn_final<<<1, 64>>>(6, (float)NN, g3, be3, nullptr, 6, 0.f, nullptr);
    k_bnrelu<<<3125, 256>>>((float*)d_out, p_u, 6);
}

// round 16
// speedup vs baseline: 1.2243x; 1.2243x over previous
#include <cuda_runtime.h>

#define NN 50000
#define EE 800000
#define RR 850000
#define EPS 1e-5f
#define GSMEM 51200   // (64*68 + 64*132) * 4 bytes

// ---------------- static scratch (no runtime allocation) --------------------
__device__ float g_xt[NN * 64];
__device__ float g_dsum[NN * 64];
__device__ float g_dsb[NN * 64];
__device__ float g_dsbT[NN * 64];
__device__ float g_msg[NN * 64];
__device__ float g_msgb[NN * 64];
__device__ float g_agg[NN * 64];
__device__ float g_tpre[NN * 64];
__device__ float g_u[NN * 64];
__device__ float g_sA[NN * 64];
__device__ float g_h2[(size_t)RR * 64];
__device__ int   g_indeg[NN];
__device__ int   g_outdeg[NN];
__device__ int   g_rowD[NN];     // CSR start offsets, edges grouped by dst
__device__ int   g_rowS[NN];     // CSR start offsets, edges grouped by src
__device__ int   g_curD[NN];
__device__ int   g_curS[NN];
__device__ int   g_csrD[EE];     // src node id per edge, grouped by dst
__device__ int2  g_permSD[EE];   // (src,dst) per src-sorted slot
__device__ int   g_part[512];    // scan partials: D at [0..195], S at [256..451]
__device__ float g_stat[8][64];  // 0/1 bn1 sum/sq, 2/3 bn2, 4/5 bnt, 6/7 bn3
__device__ float g_scale[8][64]; // 0/1 bn1 sc/sh, 2/3 bn2, 4/5 bnt, 6/7 bn3

// ---------------- helpers ----------------------------------------------------
__device__ __forceinline__ void fma2(unsigned long long& d,
                                     unsigned long long a, unsigned long long b) {
    asm("fma.rn.f32x2 %0, %1, %2, %0;" : "+l"(d) : "l"(a), "l"(b));
}
__device__ __forceinline__ unsigned long long dup2(float x) {
    unsigned long long r;
    asm("mov.b64 %0, {%1, %1};" : "=l"(r) : "f"(x));
    return r;
}
__device__ __forceinline__ unsigned long long pack2(float x, float y) {
    unsigned long long r;
    asm("mov.b64 %0, {%1, %2};" : "=l"(r) : "f"(x), "f"(y));
    return r;
}
__device__ __forceinline__ float2 unpack2(unsigned long long v) {
    float2 r;
    asm("mov.b64 {%0, %1}, %2;" : "=f"(r.x), "=f"(r.y) : "l"(v));
    return r;
}
__device__ __forceinline__ float4 add4(float4 a, float4 b) {
    return make_float4(a.x + b.x, a.y + b.y, a.z + b.z, a.w + b.w);
}
__device__ __forceinline__ float4 bnrelu4(float4 v, float4 sc, float4 sh) {
    float4 r;
    r.x = fmaxf(fmaf(v.x, sc.x, sh.x), 0.f);
    r.y = fmaxf(fmaf(v.y, sc.y, sh.y), 0.f);
    r.z = fmaxf(fmaf(v.z, sc.z, sh.z), 0.f);
    r.w = fmaxf(fmaf(v.w, sc.w, sh.w), 0.f);
    return r;
}

// ---------------- init: stats = 0, degrees = 0 -------------------------------
__global__ void k_init0() {
    int idx = blockIdx.x * 256 + threadIdx.x;        // 196*256 = 50176
    if (idx < 512) (&g_stat[0][0])[idx] = 0.f;
    if (idx < NN) { g_indeg[idx] = 0; g_outdeg[idx] = 0; }
}

// ---------------- degree counts ----------------------------------------------
__global__ void k_deg(const int* __restrict__ src, const int* __restrict__ dst) {
    int e = blockIdx.x * 256 + threadIdx.x;          // EE exact
    atomicAdd(&g_indeg[dst[e]], 1);
    atomicAdd(&g_outdeg[src[e]], 1);
}

// ---------------- scan step 1: per-block partial sums ------------------------
// D partials -> g_part[0..195]; S partials -> g_part[256..451] (segment-aligned)
__global__ void k_scan1() {
    __shared__ int sm[256];
    int b = blockIdx.x;                              // 0..391
    int isD = b < 196;
    int li = (isD ? b : b - 196) * 256 + threadIdx.x;
    const int* deg = isD ? g_indeg : g_outdeg;
    int v = (li < NN) ? deg[li] : 0;
    sm[threadIdx.x] = v;
    __syncthreads();
    for (int off = 128; off > 0; off >>= 1) {
        if (threadIdx.x < off) sm[threadIdx.x] += sm[threadIdx.x + off];
        __syncthreads();
    }
    if (threadIdx.x == 0) g_part[isD ? b : (b - 196 + 256)] = sm[0];
}

// ---------------- scan step 2: exclusive scan of partials (2 segments) -------
__global__ void k_scan2() {
    __shared__ int sm[512];
    int tid = threadIdx.x;                           // 512 threads
    int valid = (tid & 255) < 196;
    int v = valid ? g_part[tid] : 0;
    sm[tid] = v;
    __syncthreads();
    for (int off = 1; off < 256; off <<= 1) {
        int t = ((tid & 255) >= off) ? sm[tid - off] : 0;
        __syncthreads();
        sm[tid] += t;
        __syncthreads();
    }
    if (valid) g_part[tid] = sm[tid] - v;            // exclusive within segment
}

// ---------------- scan step 3: row starts + cursors --------------------------
__global__ void k_scan3() {
    __shared__ int sm[256];
    int b = blockIdx.x;
    int tid = threadIdx.x;
    int isD = b < 196;
    int li = (isD ? b : b - 196) * 256 + tid;
    const int* deg = isD ? g_indeg : g_outdeg;
    int v = (li < NN) ? deg[li] : 0;
    sm[tid] = v;
    __syncthreads();
    for (int off = 1; off < 256; off <<= 1) {
        int t = (tid >= off) ? sm[tid - off] : 0;
        __syncthreads();
        sm[tid] += t;
        __syncthreads();
    }
    int start = g_part[isD ? b : (b - 196 + 256)] + sm[tid] - v;
    if (li < NN) {
        if (isD) { g_rowD[li] = start; g_curD[li] = start; }
        else     { g_rowS[li] = start; g_curS[li] = start; }
    }
}

// ---------------- CSR fill ---------------------------------------------------
__global__ void k_fill(const int* __restrict__ src, const int* __restrict__ dst) {
    int e = blockIdx.x * 256 + threadIdx.x;          // EE exact
    int s = src[e], d = dst[e];
    int pD = atomicAdd(&g_curD[d], 1);
    g_csrD[pD] = s;
    int pS = atomicAdd(&g_curS[s], 1);
    g_permSD[pS] = make_int2(s, d);
}

// ---------------- dsum[d] = x[d] + sum_{e:dst=d} x[src] (gather) -------------
__global__ void k_dsum_g(const float4* __restrict__ x4) {
    int tid = threadIdx.x;
    int d = blockIdx.x * 16 + (tid >> 4);            // 3125*16 = NN exact
    int c4 = tid & 15;
    float4 acc = x4[(size_t)d * 16 + c4];
    int start = g_rowD[d], len = g_indeg[d];
    int j = 0;
    for (; j + 1 < len; j += 2) {
        int a0 = g_csrD[start + j], a1 = g_csrD[start + j + 1];
        float4 v0 = x4[(size_t)a0 * 16 + c4];
        float4 v1 = x4[(size_t)a1 * 16 + c4];
        acc = add4(acc, add4(v0, v1));
    }
    if (j < len) acc = add4(acc, x4[(size_t)g_csrD[start + j] * 16 + c4]);
    ((float4*)g_dsum)[(size_t)d * 16 + c4] = acc;
}

// ---------------- N-row GEMM: out = in1@W1 [+ in2@W2] [+bias]; f32x2 FMA -----
__global__ void __launch_bounds__(256) k_gemm2(float* __restrict__ out,
                                               const float* __restrict__ in1,
                                               const float* __restrict__ W1,
                                               const float* __restrict__ in2,
                                               const float* __restrict__ W2,
                                               const float* __restrict__ bias,
                                               int relu, int si, int insc,
                                               float* __restrict__ out2,
                                               const float* __restrict__ in1b,
                                               const float* __restrict__ W1b,
                                               float* __restrict__ out3,
                                               const float* __restrict__ in1c,
                                               const float* __restrict__ W1c) {
    extern __shared__ float dynS[];
    float* Ws = dynS;              // [64][68]
    float* inT = dynS + 64 * 68;   // [64][132]
    __shared__ float statS[128];
    int tid = threadIdx.x;
    if (tid < 128) statS[tid] = 0.f;
    const float* inA = in1;
    const float* WA = W1;
    float* outp = out;
    int base;
    if (out3) {
        int third = gridDim.x / 3;
        int sgm = blockIdx.x / third;
        base = (blockIdx.x - sgm * third) * 128;
        if (sgm == 1) { inA = in1b; WA = W1b; outp = out2; }
        else if (sgm == 2) { inA = in1c; WA = W1c; outp = out3; }
    } else if (out2) {
        int half = gridDim.x >> 1;
        if (blockIdx.x >= half) {
            inA = in1b; WA = W1b; outp = out2;
            base = (blockIdx.x - half) * 128;
        } else base = blockIdx.x * 128;
    } else base = blockIdx.x * 128;
    int rg = tid >> 3, cg = tid & 7;
    int r0 = rg * 4, c0 = cg * 8;
    unsigned long long acc[4][4];
#pragma unroll
    for (int rr = 0; rr < 4; rr++)
#pragma unroll
        for (int jp = 0; jp < 4; jp++)
            acc[rr][jp] = bias ? pack2(bias[c0 + jp * 2], bias[c0 + jp * 2 + 1]) : 0ull;

#pragma unroll 1
    for (int p = 0; p < 2; p++) {
        const float* in = p ? in2 : inA;
        const float* W = p ? W2 : WA;
        if (!in) break;
        if (p) __syncthreads();
        for (int i = tid; i < 4096; i += 256) Ws[(i >> 6) * 68 + (i & 63)] = W[i];
        const float4* in4 = (const float4*)in;
        int xf = (p == 0 && insc >= 0);
        for (int i = tid; i < 2048; i += 256) {
            int r = i & 127, c4 = i >> 7;
            float4 v = make_float4(0.f, 0.f, 0.f, 0.f);
            if (base + r < NN) {
                v = in4[(size_t)(base + r) * 16 + c4];
                if (xf) v = bnrelu4(v, ((const float4*)g_scale[insc])[c4],
                                    ((const float4*)g_scale[insc + 1])[c4]);
            }
            int c = c4 * 4;
            inT[c * 132 + r] = v.x; inT[(c + 1) * 132 + r] = v.y;
            inT[(c + 2) * 132 + r] = v.z; inT[(c + 3) * 132 + r] = v.w;
        }
        __syncthreads();
#pragma unroll 4
        for (int k = 0; k < 64; k++) {
            float4 a4 = *(const float4*)&inT[k * 132 + r0];
            ulonglong2 w01 = *(const ulonglong2*)&Ws[k * 68 + c0];
            ulonglong2 w23 = *(const ulonglong2*)&Ws[k * 68 + c0 + 4];
            unsigned long long wp[4] = { w01.x, w01.y, w23.x, w23.y };
            unsigned long long ap[4] = { dup2(a4.x), dup2(a4.y), dup2(a4.z), dup2(a4.w) };
#pragma unroll
            for (int rr = 0; rr < 4; rr++)
#pragma unroll
                for (int jp = 0; jp < 4; jp++)
                    fma2(acc[rr][jp], ap[rr], wp[jp]);
        }
    }
    float lsum[8], lsq[8];
#pragma unroll
    for (int j = 0; j < 8; j++) { lsum[j] = 0.f; lsq[j] = 0.f; }
#pragma unroll
    for (int rr = 0; rr < 4; rr++) {
        int gr = base + r0 + rr;
        if (gr >= NN) break;
        float o[8];
#pragma unroll
        for (int jp = 0; jp < 4; jp++) {
            float2 u = unpack2(acc[rr][jp]);
            o[jp * 2] = u.x; o[jp * 2 + 1] = u.y;
        }
        if (relu) {
#pragma unroll
            for (int j = 0; j < 8; j++) o[j] = fmaxf(o[j], 0.f);
        }
        if (si >= 0) {
#pragma unroll
            for (int j = 0; j < 8; j++) { lsum[j] += o[j]; lsq[j] += o[j] * o[j]; }
        }
        float4* op = (float4*)(outp + (size_t)gr * 64 + c0);
        op[0] = make_float4(o[0], o[1], o[2], o[3]);
        op[1] = make_float4(o[4], o[5], o[6], o[7]);
    }
    if (si >= 0) {
        int lane = tid & 31;
#pragma unroll
        for (int j = 0; j < 8; j++) {
            float s_ = lsum[j], q_ = lsq[j];
            s_ += __shfl_xor_sync(0xFFFFFFFFu, s_, 8);
            s_ += __shfl_xor_sync(0xFFFFFFFFu, s_, 16);
            q_ += __shfl_xor_sync(0xFFFFFFFFu, q_, 8);
            q_ += __shfl_xor_sync(0xFFFFFFFFu, q_, 16);
            if (lane < 8) {
                atomicAdd(&statS[c0 + j], s_);
                atomicAdd(&statS[64 + c0 + j], q_);
            }
        }
        __syncthreads();
        if (tid < 64) {
            atomicAdd(&g_stat[si][tid], statS[tid]);
            atomicAdd(&g_stat[si + 1][tid], statS[64 + tid]);
        }
    }
}

// ---------------- BN1 stats: algebraic node-level pass -----------------------
__global__ void k_bn1_alg(const float* __restrict__ b_unite) {
    __shared__ float st[128];
    int tid = threadIdx.x;
    if (tid < 128) st[tid] = 0.f;
    __syncthreads();
    int idx = blockIdx.x * 256 + tid;                // NN*16 exact
    int i = idx >> 4, c4 = idx & 15;
    float4 X = ((const float4*)g_xt)[idx];
    float4 D = ((const float4*)g_dsb)[idx];
    float4 T = ((const float4*)g_dsbT)[idx];
    float4 b = ((const float4*)b_unite)[c4];
    float od = (float)g_outdeg[i], id = (float)g_indeg[i];
    float s1v[4], s2v[4];
    {
        float xs[4] = { X.x, X.y, X.z, X.w };
        float ds[4] = { D.x, D.y, D.z, D.w };
        float ts[4] = { T.x, T.y, T.z, T.w };
        float bs[4] = { b.x, b.y, b.z, b.w };
#pragma unroll
        for (int k = 0; k < 4; k++) {
            float v = xs[k] + ds[k] + bs[k];
            float e1 = od * xs[k] + id * ds[k];
            s1v[k] = v + e1;
            s2v[k] = v * v + od * xs[k] * xs[k] + id * ds[k] * ds[k]
                   + 2.f * (ts[k] - xs[k]) * ds[k] + 2.f * bs[k] * e1;
        }
    }
#pragma unroll
    for (int k = 0; k < 4; k++) {
        s1v[k] += __shfl_xor_sync(0xFFFFFFFFu, s1v[k], 16);
        s2v[k] += __shfl_xor_sync(0xFFFFFFFFu, s2v[k], 16);
    }
    if ((tid & 16) == 0) {
#pragma unroll
        for (int k = 0; k < 4; k++) {
            atomicAdd(&st[c4 * 4 + k], s1v[k]);
            atomicAdd(&st[64 + c4 * 4 + k], s2v[k]);
        }
    }
    __syncthreads();
    if (tid < 64) {
        atomicAdd(&g_stat[0][tid], st[tid]);
        atomicAdd(&g_stat[1][tid], st[64 + tid]);
    }
}

// ---------------- BN finalize into scale/shift -------------------------------
__global__ void k_bn_final(int si, float cnt, const float* __restrict__ g,
                           const float* __restrict__ be, const float* __restrict__ pb,
                           int oi, float cntE, const float* __restrict__ pe) {
    int c = threadIdx.x;
    float s = g_stat[si][c], q = g_stat[si + 1][c];
    if (pe) { s += cntE * pe[c]; q += cntE * pe[c] * pe[c]; }
    float m = s / cnt;
    float v = q / cnt - m * m;
    float sc = g[c] * rsqrtf(v + EPS);
    float sh = be[c] - m * sc;
    if (pb) sh += pb[c] * sc;
    g_scale[oi][c] = sc;
    g_scale[oi + 1][c] = sh;
}

// ---------------- s[d] = hn(d,d) + sum_{e:dst=d} hn(src,d) (gather) ----------
__global__ void k_s_g() {
    int tid = threadIdx.x;
    int d = blockIdx.x * 16 + (tid >> 4);
    int c4 = tid & 15;
    const float4* xt4 = (const float4*)g_xt;
    float4 dsb_d = ((const float4*)g_dsb)[(size_t)d * 16 + c4];
    float4 sc = ((const float4*)g_scale[0])[c4];
    float4 sh = ((const float4*)g_scale[1])[c4];
    float4 acc = bnrelu4(add4(xt4[(size_t)d * 16 + c4], dsb_d), sc, sh);
    int start = g_rowD[d], len = g_indeg[d];
    int j = 0;
    for (; j + 1 < len; j += 2) {
        int a0 = g_csrD[start + j], a1 = g_csrD[start + j + 1];
        float4 v0 = xt4[(size_t)a0 * 16 + c4];
        float4 v1 = xt4[(size_t)a1 * 16 + c4];
        acc = add4(acc, add4(bnrelu4(add4(v0, dsb_d), sc, sh),
                             bnrelu4(add4(v1, dsb_d), sc, sh)));
    }
    if (j < len)
        acc = add4(acc, bnrelu4(add4(xt4[(size_t)g_csrD[start + j] * 16 + c4], dsb_d), sc, sh));
    ((float4*)g_sA)[(size_t)d * 16 + c4] = acc;
}

// ---------------- msg[d] = sum_{e:dst=d} s[src] (gather) ---------------------
__global__ void k_msg_g() {
    int tid = threadIdx.x;
    int d = blockIdx.x * 16 + (tid >> 4);
    int c4 = tid & 15;
    const float4* s4 = (const float4*)g_sA;
    float4 acc = make_float4(0.f, 0.f, 0.f, 0.f);
    int start = g_rowD[d], len = g_indeg[d];
    int j = 0;
    for (; j + 1 < len; j += 2) {
        int a0 = g_csrD[start + j], a1 = g_csrD[start + j + 1];
        acc = add4(acc, add4(s4[(size_t)a0 * 16 + c4], s4[(size_t)a1 * 16 + c4]));
    }
    if (j < len) acc = add4(acc, s4[(size_t)g_csrD[start + j] * 16 + c4]);
    ((float4*)g_msg)[(size_t)d * 16 + c4] = acc;
}

// ---------------- hot: h2_pre (src-permuted edge rows) + fused BN2 stats -----
__global__ void __launch_bounds__(256) k_h2(const float* __restrict__ Wg) {
    extern __shared__ float dynS[];
    float* Ws = dynS;              // [64][68]
    float* hnT = dynS + 64 * 68;   // [64][132]
    __shared__ int domS[128];
    __shared__ float statS[128];
    int tid = threadIdx.x;
    for (int i = tid; i < 4096; i += 256) Ws[(i >> 6) * 68 + (i & 63)] = Wg[i];
    if (tid < 128) statS[tid] = 0.f;
    int rg = tid >> 3, cg = tid & 7;
    int r0 = rg * 4, c0 = cg * 8;
    const float4* xt4 = (const float4*)g_xt;
    const float4* db4 = (const float4*)g_dsb;
    const float4* sc4 = (const float4*)g_scale[0];
    const float4* sh4 = (const float4*)g_scale[1];
    const float4* mb4 = (const float4*)g_msgb;
    float lsum[8], lsq[8];
#pragma unroll
    for (int j = 0; j < 8; j++) { lsum[j] = 0.f; lsq[j] = 0.f; }
    __syncthreads();

    for (int t = 0; t < 4; t++) {
        long base = ((long)blockIdx.x * 4 + t) * 128;
        if (base >= RR) break;
        for (int i = tid; i < 2048; i += 256) {
            int r = i & 127, c4 = i >> 7;
            long gr = base + r;
            float4 v = make_float4(0.f, 0.f, 0.f, 0.f);
            int d = 0;
            if (gr < RR) {
                int a;
                if (gr < NN) { a = (int)gr; d = a; }
                else { int2 sd = g_permSD[gr - NN]; a = sd.x; d = sd.y; }
                v = bnrelu4(add4(xt4[(size_t)a * 16 + c4], db4[(size_t)d * 16 + c4]),
                            sc4[c4], sh4[c4]);
            }
            if (c4 == 0) domS[r] = d;
            int c = c4 * 4;
            hnT[c * 132 + r] = v.x; hnT[(c + 1) * 132 + r] = v.y;
            hnT[(c + 2) * 132 + r] = v.z; hnT[(c + 3) * 132 + r] = v.w;
        }
        __syncthreads();
        unsigned long long acc[4][4];
#pragma unroll
        for (int rr = 0; rr < 4; rr++)
#pragma unroll
            for (int jp = 0; jp < 4; jp++) acc[rr][jp] = 0ull;
#pragma unroll 4
        for (int k = 0; k < 64; k++) {
            float4 a4 = *(const float4*)&hnT[k * 132 + r0];
            ulonglong2 w01 = *(const ulonglong2*)&Ws[k * 68 + c0];
            ulonglong2 w23 = *(const ulonglong2*)&Ws[k * 68 + c0 + 4];
            unsigned long long wp[4] = { w01.x, w01.y, w23.x, w23.y };
            unsigned long long ap[4] = { dup2(a4.x), dup2(a4.y), dup2(a4.z), dup2(a4.w) };
#pragma unroll
            for (int rr = 0; rr < 4; rr++)
#pragma unroll
                for (int jp = 0; jp < 4; jp++)
                    fma2(acc[rr][jp], ap[rr], wp[jp]);
        }
#pragma unroll
        for (int rr = 0; rr < 4; rr++) {
            long gr = base + r0 + rr;
            if (gr >= RR) break;
            int dm = domS[r0 + rr];
            float4 m0 = mb4[(size_t)dm * 16 + cg * 2];
            float4 m1 = mb4[(size_t)dm * 16 + cg * 2 + 1];
            float mv[8] = { m0.x, m0.y, m0.z, m0.w, m1.x, m1.y, m1.z, m1.w };
            float o[8];
#pragma unroll
            for (int jp = 0; jp < 4; jp++) {
                float2 u = unpack2(acc[rr][jp]);
                o[jp * 2] = u.x + mv[jp * 2];
                o[jp * 2 + 1] = u.y + mv[jp * 2 + 1];
            }
#pragma unroll
            for (int j = 0; j < 8; j++) { lsum[j] += o[j]; lsq[j] += o[j] * o[j]; }
            float4* op = (float4*)(g_h2 + (size_t)gr * 64 + c0);
            op[0] = make_float4(o[0], o[1], o[2], o[3]);
            op[1] = make_float4(o[4], o[5], o[6], o[7]);
        }
        __syncthreads();
    }
    int lane = tid & 31;
#pragma unroll
    for (int j = 0; j < 8; j++) {
        float s_ = lsum[j], q_ = lsq[j];
        s_ += __shfl_xor_sync(0xFFFFFFFFu, s_, 8);
        s_ += __shfl_xor_sync(0xFFFFFFFFu, s_, 16);
        q_ += __shfl_xor_sync(0xFFFFFFFFu, q_, 8);
        q_ += __shfl_xor_sync(0xFFFFFFFFu, q_, 16);
        if (lane < 8) {
            atomicAdd(&statS[c0 + j], s_);
            atomicAdd(&statS[64 + c0 + j], q_);
        }
    }
    __syncthreads();
    if (tid < 64) {
        atomicAdd(&g_stat[2][tid], statS[tid]);
        atomicAdd(&g_stat[3][tid], statS[64 + tid]);
    }
}

// ---------------- agg[i] = bn2relu(h2[i]) + sum of contiguous src rows -------
__global__ void k_agg_g() {
    int tid = threadIdx.x;
    int i = blockIdx.x * 16 + (tid >> 4);
    int c4 = tid & 15;
    const float4* h4 = (const float4*)g_h2;
    float4 sc = ((const float4*)g_scale[2])[c4];
    float4 sh = ((const float4*)g_scale[3])[c4];
    float4 acc = bnrelu4(h4[(size_t)i * 16 + c4], sc, sh);
    size_t rbase = (size_t)NN + g_rowS[i];
    int len = g_outdeg[i];
    int j = 0;
    for (; j + 1 < len; j += 2) {
        float4 v0 = h4[(rbase + j) * 16 + c4];
        float4 v1 = h4[(rbase + j + 1) * 16 + c4];
        acc = add4(acc, add4(bnrelu4(v0, sc, sh), bnrelu4(v1, sc, sh)));
    }
    if (j < len)
        acc = add4(acc, bnrelu4(h4[(rbase + j) * 16 + c4], sc, sh));
    ((float4*)g_agg)[(size_t)i * 16 + c4] = acc;
}

// ---------------- out = relu(in * scale + shift) -----------------------------
__global__ void k_bnrelu(float* __restrict__ out, const float* __restrict__ in, int sidx) {
    int idx = blockIdx.x * 256 + threadIdx.x;        // NN*16 exact
    int c4 = idx & 15;
    float4 v = ((const float4*)in)[idx];
    ((float4*)out)[idx] = bnrelu4(v, ((const float4*)g_scale[0] + (size_t)sidx * 16)[c4],
                                  ((const float4*)g_scale[0] + (size_t)(sidx + 1) * 16)[c4]);
}

extern "C" void kernel_launch(void* const* d_in, const int* in_sizes, int n_in,
                              void* d_out, int out_size) {
    const float* x   = (const float*)d_in[0];
    const int*   ei  = (const int*)d_in[1];
    const int*   src = ei;
    const int*   dst = ei + EE;
    const float* Wu  = (const float*)d_in[2];
    const float* bu  = (const float*)d_in[3];
    const float* g1  = (const float*)d_in[4];
    const float* be1 = (const float*)d_in[5];
    const float* Wg  = (const float*)d_in[6];
    const float* bg  = (const float*)d_in[7];
    const float* g2  = (const float*)d_in[8];
    const float* be2 = (const float*)d_in[9];
    const float* Wt  = (const float*)d_in[10];
    const float* bt  = (const float*)d_in[11];
    const float* Wl  = (const float*)d_in[12];
    const float* bl  = (const float*)d_in[13];
    const float* g3  = (const float*)d_in[14];
    const float* be3 = (const float*)d_in[15];

    static float *p_xt = nullptr, *p_dsum, *p_dsb, *p_dsbT, *p_msg, *p_msgb,
                 *p_agg, *p_tpre, *p_u, *p_h2;
    if (!p_xt) {
        cudaGetSymbolAddress((void**)&p_xt, g_xt);
        cudaGetSymbolAddress((void**)&p_dsum, g_dsum);
        cudaGetSymbolAddress((void**)&p_dsb, g_dsb);
        cudaGetSymbolAddress((void**)&p_dsbT, g_dsbT);
        cudaGetSymbolAddress((void**)&p_msg, g_msg);
        cudaGetSymbolAddress((void**)&p_msgb, g_msgb);
        cudaGetSymbolAddress((void**)&p_agg, g_agg);
        cudaGetSymbolAddress((void**)&p_tpre, g_tpre);
        cudaGetSymbolAddress((void**)&p_u, g_u);
        cudaGetSymbolAddress((void**)&p_h2, g_h2);
        cudaFuncSetAttribute(k_gemm2, cudaFuncAttributeMaxDynamicSharedMemorySize, GSMEM);
        cudaFuncSetAttribute(k_h2, cudaFuncAttributeMaxDynamicSharedMemorySize, GSMEM);
    }

    // CSR build (segment-aligned scan)
    k_init0<<<196, 256>>>();
    k_deg<<<3125, 256>>>(src, dst);
    k_scan1<<<392, 256>>>();
    k_scan2<<<1, 512>>>();
    k_scan3<<<392, 256>>>();
    k_fill<<<3125, 256>>>(src, dst);

    // unite: gather dsum, triple GEMM, algebraic BN1
    k_dsum_g<<<3125, 256>>>((const float4*)x);
    k_gemm2<<<1173, 256, GSMEM>>>(p_xt, x, Wu, nullptr, nullptr, nullptr, 0, -1, -1,
                                  p_dsb, p_dsum, Wu + 4096,
                                  p_dsbT, p_dsum, Wu);
    k_bn1_alg<<<3125, 256>>>(bu);
    k_bn_final<<<1, 64>>>(0, (float)RR, g1, be1, bu, 0, (float)EE, bu);

    // gconv: gather s, gather msg, msgb GEMM, h2 (src-permuted edge rows)
    k_s_g<<<3125, 256>>>();
    k_msg_g<<<3125, 256>>>();
    k_gemm2<<<391, 256, GSMEM>>>(p_msgb, p_msg, Wg + 4096, nullptr, nullptr, bg, 0, -1, -1,
                                 nullptr, nullptr, nullptr, nullptr, nullptr, nullptr);
    k_h2<<<1661, 256, GSMEM>>>(Wg);
    k_bn_final<<<1, 64>>>(2, (float)RR, g2, be2, nullptr, 2, 0.f, nullptr);

    // transfer: streaming agg; dual GEMM reads u on-the-fly from h2 self rows
    // (in1 = g_h2 rows 0..NN-1 with bn2relu input transform, insc=2)
    k_agg_g<<<3125, 256>>>();
    k_gemm2<<<391, 256, GSMEM>>>(p_tpre, p_h2, Wt, p_agg, Wt + 4096, bt, 0, 4, 2,
                                 nullptr, nullptr, nullptr, nullptr, nullptr, nullptr);
    k_bn_final<<<1, 64>>>(4, (float)NN, g2, be2, nullptr, 4, 0.f, nullptr);

    // final linear with fused input bnrelu(t) transform; relu + BN3 stats
    k_gemm2<<<391, 256, GSMEM>>>(p_u, p_tpre, Wl, nullptr, nullptr, bl, 1, 6, 4,
                                 nullptr, nullptr, nullptr, nullptr, nullptr, nullptr);
    k_bn_final<<<1, 64>>>(6, (float)NN, g3, be3, nullptr, 6, 0.f, nullptr);
    k_bnrelu<<<3125, 256>>>((float*)d_out, p_u, 6);
}